// round 12
// baseline (speedup 1.0000x reference)
#include <cuda_runtime.h>
#include <cuda.h>
#include <math.h>
#include <stdint.h>

#define BATCH 16
#define SEQ   2048
#define DIM   128
#define MTOT  (BATCH * SEQ)

// ---------------- scratch (allocation-free device globals) ----------------
__device__ float g_h[MTOT * DIM];
__device__ float g_a[MTOT * DIM];

__device__ __forceinline__ float sigmoidf_(float v) {
    return 1.0f / (1.0f + __expf(-v));
}
__device__ __forceinline__ uint32_t smem_u32(const void* p) {
    uint32_t a;
    asm("{ .reg .u64 t; cvta.to.shared.u64 t, %1; cvt.u32.u64 %0, t; }" : "=r"(a) : "l"(p));
    return a;
}
// truncation split: hi = top tf32 bits, lo = exact remainder (2 ops).
__device__ __forceinline__ void tsplit(float x, uint32_t& hi, uint32_t& lo) {
    hi = __float_as_uint(x) & 0xFFFFE000u;
    lo = __float_as_uint(x - __uint_as_float(hi));
}
__device__ __forceinline__ void mma_tf32(float* d, const uint32_t* a,
                                         uint32_t b0, uint32_t b1) {
    asm volatile("mma.sync.aligned.m16n8k8.row.col.f32.tf32.tf32.f32 "
                 "{%0,%1,%2,%3}, {%4,%5,%6,%7}, {%8,%9}, {%0,%1,%2,%3};"
                 : "+f"(d[0]), "+f"(d[1]), "+f"(d[2]), "+f"(d[3])
                 : "r"(a[0]), "r"(a[1]), "r"(a[2]), "r"(a[3]), "r"(b0), "r"(b1));
}
// ---- TMA + mbarrier ----
__device__ __forceinline__ void tma2d(uint32_t dst, const void* map,
                                      int c0, int c1, uint32_t mbar) {
    asm volatile("cp.async.bulk.tensor.2d.shared::cta.global.tile.mbarrier::complete_tx::bytes "
                 "[%0], [%1, {%2, %3}], [%4];"
                 :: "r"(dst), "l"(map), "r"(c0), "r"(c1), "r"(mbar) : "memory");
}
__device__ __forceinline__ void tma3d(uint32_t dst, const void* map,
                                      int c0, int c1, int c2, uint32_t mbar) {
    asm volatile("cp.async.bulk.tensor.3d.shared::cta.global.tile.mbarrier::complete_tx::bytes "
                 "[%0], [%1, {%2, %3, %4}], [%5];"
                 :: "r"(dst), "l"(map), "r"(c0), "r"(c1), "r"(c2), "r"(mbar) : "memory");
}
__device__ __forceinline__ void mbar_init(uint32_t mbar, uint32_t cnt) {
    asm volatile("mbarrier.init.shared.b64 [%0], %1;" :: "r"(mbar), "r"(cnt) : "memory");
}
__device__ __forceinline__ void mbar_expect(uint32_t mbar, uint32_t bytes) {
    asm volatile("mbarrier.arrive.expect_tx.shared.b64 _, [%0], %1;"
                 :: "r"(mbar), "r"(bytes) : "memory");
}
__device__ __forceinline__ void mbar_wait(uint32_t mbar, uint32_t parity) {
    uint32_t done;
    asm volatile("{\n\t.reg .pred p;\n\t"
                 "mbarrier.try_wait.parity.acquire.cta.shared::cta.b64 p, [%1], %2;\n\t"
                 "selp.b32 %0, 1, 0, p;\n\t}"
                 : "=r"(done) : "r"(mbar), "r"(parity) : "memory");
    while (!done) {
        asm volatile("{\n\t.reg .pred p;\n\t"
                     "mbarrier.try_wait.parity.acquire.cta.shared::cta.b64 p, [%1], %2;\n\t"
                     "selp.b32 %0, 1, 0, p;\n\t}"
                     : "=r"(done) : "r"(mbar), "r"(parity) : "memory");
    }
}

// ===========================================================================
// Kernel 1a: encode (UNCHANGED from the 789.6us best — 128x128 tile)
// ===========================================================================
#define NSTAGE     3
#define STAGE_B    32768u
#define DATA_OFF   1024u
#define SMEM_BYTES (DATA_OFF + NSTAGE * STAGE_B)

__global__ void __launch_bounds__(256, 2)
encode_tma(const __grid_constant__ CUtensorMap mA1,
           const __grid_constant__ CUtensorMap mB1,
           const float* __restrict__ bias1, float* __restrict__ Cout)
{
    extern __shared__ __align__(1024) char smem[];
    const uint32_t sb = smem_u32(smem);

    const int tid = threadIdx.x, lane = tid & 31, warp = tid >> 5;
    const int wm = warp & 3, wn = warp >> 2;
    const int mbase = wm * 32, nbase = wn * 64;
    const int lq = lane >> 2, lt = lane & 3;
    const size_t rowTile = (size_t)blockIdx.x * 128;
    constexpr int NC = 4;

    if (tid == 0) {
#pragma unroll
        for (int s = 0; s < NSTAGE; s++) mbar_init(sb + s * 8, 1);
    }
    __syncthreads();

    auto issue = [&](int c) {
        const int s = c % NSTAGE;
        const uint32_t bar  = sb + s * 8;
        const uint32_t dstA = sb + DATA_OFF + s * STAGE_B;
        const uint32_t dstB = dstA + 16384u;
        const int k0 = c * 32;
        mbar_expect(bar, STAGE_B);
        tma2d(dstA, &mA1, k0, (int)(blockIdx.x * 128), bar);
#pragma unroll
        for (int i = 0; i < 4; i++)
            tma2d(dstB + i * 4096u, &mB1, i * 32, k0, bar);
    };

    float acc[2][8][4];
#pragma unroll
    for (int mi = 0; mi < 2; mi++)
#pragma unroll
        for (int j = 0; j < 8; j++)
#pragma unroll
            for (int q = 0; q < 4; q++) acc[mi][j][q] = 0.0f;

    const uint32_t aswz = (uint32_t)lq << 4;
    uint32_t bcol0[8], bcol1[8];
#pragma unroll
    for (int j = 0; j < 8; j++) {
        const int n  = nbase + j * 8 + lq;
        const uint32_t nb = (uint32_t)((n & 31) * 4);
        bcol0[j] = ((uint32_t)(n >> 5)) * 4096u + (nb ^ ((uint32_t)lt << 4));
        bcol1[j] = ((uint32_t)(n >> 5)) * 4096u + (nb ^ (((uint32_t)(lt + 4)) << 4));
    }

    if (tid == 0) { issue(0); issue(1); issue(2); }

#pragma unroll 1
    for (int c = 0; c < NC; ++c) {
        const int s = c % NSTAGE;
        mbar_wait(sb + s * 8, (uint32_t)((c / NSTAGE) & 1));
        const char* As = smem + DATA_OFF + s * STAGE_B;
        const char* Bs = As + 16384;

#pragma unroll
        for (int kk = 0; kk < 32; kk += 8) {
            const int kt0 = kk + lt, kt1 = kt0 + 4;
            uint32_t ah[2][4], al[2][4];
#pragma unroll
            for (int mi = 0; mi < 2; mi++) {
                const int r0 = mbase + mi * 16 + lq, r1 = r0 + 8;
                const uint32_t c0 = ((uint32_t)(kt0 * 4)) ^ aswz;
                const uint32_t c1 = ((uint32_t)(kt1 * 4)) ^ aswz;
                tsplit(*(const float*)(As + r0 * 128 + c0), ah[mi][0], al[mi][0]);
                tsplit(*(const float*)(As + r1 * 128 + c0), ah[mi][1], al[mi][1]);
                tsplit(*(const float*)(As + r0 * 128 + c1), ah[mi][2], al[mi][2]);
                tsplit(*(const float*)(As + r1 * 128 + c1), ah[mi][3], al[mi][3]);
            }
#pragma unroll
            for (int j = 0; j < 8; j++) {
                uint32_t bh0, bl0, bh1, bl1;
                tsplit(*(const float*)(Bs + kt0 * 128 + bcol0[j]), bh0, bl0);
                tsplit(*(const float*)(Bs + kt1 * 128 + bcol1[j]), bh1, bl1);
#pragma unroll
                for (int mi = 0; mi < 2; mi++) {
                    mma_tf32(acc[mi][j], ah[mi], bh0, bh1);
                    mma_tf32(acc[mi][j], ah[mi], bl0, bl1);
                    mma_tf32(acc[mi][j], al[mi], bh0, bh1);
                }
            }
        }
        __syncthreads();
        if (c + NSTAGE < NC && tid == 0) issue(c + NSTAGE);
    }

#pragma unroll
    for (int mi = 0; mi < 2; mi++) {
        const int rA = mbase + mi * 16 + lq;
        const size_t gr0 = rowTile + rA, gr1 = gr0 + 8;
#pragma unroll
        for (int j = 0; j < 8; j++) {
            const int col = nbase + j * 8 + lt * 2;
            float o[4];
#pragma unroll
            for (int q = 0; q < 4; q++) {
                const int cc = col + (q & 1);
                o[q] = fmaxf(acc[mi][j][q] + bias1[cc], 0.0f);
            }
            *(float2*)&Cout[gr0 * 128 + col] = make_float2(o[0], o[1]);
            *(float2*)&Cout[gr1 * 128 + col] = make_float2(o[2], o[3]);
        }
    }
}

// ===========================================================================
// Kernel 1b: spmm v3 — 128x64 tile, 8 warps (4Mx2N, warp 32x32, acc 32 regs),
// 3 CTAs/SM (24KB stages x3 = 73KB), 6 warps/SMSP. Same k-order => identical
// numerics. grid = (32 = rowTile*2 + colTile, 16 batches).
// ===========================================================================
#define S64_STAGE  24576u
#define S64_SMEM   (1024u + 3u * S64_STAGE)   // 74752

__global__ void __launch_bounds__(256, 3)
spmm_tma64(const __grid_constant__ CUtensorMap mA1,
           const __grid_constant__ CUtensorMap mB1,
           const float* __restrict__ ffd, float* __restrict__ Cout)
{
    extern __shared__ __align__(1024) char smem[];
    const uint32_t sb = smem_u32(smem);

    const int tid = threadIdx.x, lane = tid & 31, warp = tid >> 5;
    const int wm = warp & 3, wn = warp >> 2;          // 4M x 2N
    const int mbase = wm * 32, nbase = wn * 32;
    const int lq = lane >> 2, lt = lane & 3;

    const int rt = (int)(blockIdx.x >> 1);
    const int ct = (int)(blockIdx.x & 1);
    const int b  = (int)blockIdx.y;
    const size_t rowTile = (size_t)b * SEQ + (size_t)rt * 128;
    const int colOff = ct * 64;
    constexpr int NC = SEQ / 32;                       // 64

    if (tid == 0) {
#pragma unroll
        for (int s = 0; s < NSTAGE; s++) mbar_init(sb + s * 8, 1);
    }
    __syncthreads();

    auto issue = [&](int c) {
        const int s = c % NSTAGE;
        const uint32_t bar  = sb + s * 8;
        const uint32_t dstA = sb + DATA_OFF + s * S64_STAGE;
        const uint32_t dstB = dstA + 16384u;
        const int k0 = c * 32;
        mbar_expect(bar, S64_STAGE);
        tma3d(dstA, &mA1, k0, rt * 128, b, bar);
#pragma unroll
        for (int i = 0; i < 2; i++)
            tma2d(dstB + i * 4096u, &mB1, colOff + i * 32, b * SEQ + k0, bar);
    };

    float acc[2][4][4];
#pragma unroll
    for (int mi = 0; mi < 2; mi++)
#pragma unroll
        for (int j = 0; j < 4; j++)
#pragma unroll
            for (int q = 0; q < 4; q++) acc[mi][j][q] = 0.0f;

    const uint32_t aswz = (uint32_t)lq << 4;
    uint32_t bcol0[4], bcol1[4];
#pragma unroll
    for (int j = 0; j < 4; j++) {
        const int n  = nbase + j * 8 + lq;             // 0..63
        const uint32_t nb = (uint32_t)((n & 31) * 4);
        bcol0[j] = ((uint32_t)(n >> 5)) * 4096u + (nb ^ ((uint32_t)lt << 4));
        bcol1[j] = ((uint32_t)(n >> 5)) * 4096u + (nb ^ (((uint32_t)(lt + 4)) << 4));
    }

    if (tid == 0) { issue(0); issue(1); issue(2); }

#pragma unroll 1
    for (int c = 0; c < NC; ++c) {
        const int s = c % NSTAGE;
        mbar_wait(sb + s * 8, (uint32_t)((c / NSTAGE) & 1));
        const char* As = smem + DATA_OFF + s * S64_STAGE;
        const char* Bs = As + 16384;

#pragma unroll
        for (int kk = 0; kk < 32; kk += 8) {
            const int kt0 = kk + lt, kt1 = kt0 + 4;
            uint32_t ah[2][4], al[2][4];
#pragma unroll
            for (int mi = 0; mi < 2; mi++) {
                const int r0 = mbase + mi * 16 + lq, r1 = r0 + 8;
                const uint32_t c0 = ((uint32_t)(kt0 * 4)) ^ aswz;
                const uint32_t c1 = ((uint32_t)(kt1 * 4)) ^ aswz;
                tsplit(*(const float*)(As + r0 * 128 + c0), ah[mi][0], al[mi][0]);
                tsplit(*(const float*)(As + r1 * 128 + c0), ah[mi][1], al[mi][1]);
                tsplit(*(const float*)(As + r0 * 128 + c1), ah[mi][2], al[mi][2]);
                tsplit(*(const float*)(As + r1 * 128 + c1), ah[mi][3], al[mi][3]);
            }
#pragma unroll
            for (int j = 0; j < 4; j++) {
                uint32_t bh0, bl0, bh1, bl1;
                tsplit(*(const float*)(Bs + kt0 * 128 + bcol0[j]), bh0, bl0);
                tsplit(*(const float*)(Bs + kt1 * 128 + bcol1[j]), bh1, bl1);
#pragma unroll
                for (int mi = 0; mi < 2; mi++) {
                    mma_tf32(acc[mi][j], ah[mi], bh0, bh1);
                    mma_tf32(acc[mi][j], ah[mi], bl0, bl1);
                    mma_tf32(acc[mi][j], al[mi], bh0, bh1);
                }
            }
        }
        __syncthreads();
        if (c + NSTAGE < NC && tid == 0) issue(c + NSTAGE);
    }

#pragma unroll
    for (int mi = 0; mi < 2; mi++) {
        const int rA = mbase + mi * 16 + lq;
        const size_t gr0 = rowTile + rA, gr1 = gr0 + 8;
        const float s0 = 1.0f + ffd[gr0];
        const float s1 = 1.0f + ffd[gr1];
#pragma unroll
        for (int j = 0; j < 4; j++) {
            const int col = colOff + nbase + j * 8 + lt * 2;
            float o[4];
#pragma unroll
            for (int q = 0; q < 4; q++)
                o[q] = acc[mi][j][q] * ((q < 2) ? s0 : s1);
            *(float2*)&Cout[gr0 * 128 + col] = make_float2(o[0], o[1]);
            *(float2*)&Cout[gr1 * 128 + col] = make_float2(o[2], o[3]);
        }
    }
}

// ===========================================================================
// Kernel 2: fused GRU gates v2.1 (UNCHANGED — round-9 best)
// ===========================================================================
#define G_A    1024u
#define G_H    (G_A + 32768u)
#define G_W    (G_H + 32768u)
#define G_SMEM (G_W + 2u * 16384u)    // 99328

__global__ void __launch_bounds__(256, 2)
fused_gate(const __grid_constant__ CUtensorMap mA,
           const __grid_constant__ CUtensorMap mH,
           const __grid_constant__ CUtensorMap mWz0,
           const __grid_constant__ CUtensorMap mWz1,
           const __grid_constant__ CUtensorMap mWr0,
           const __grid_constant__ CUtensorMap mWr1,
           const __grid_constant__ CUtensorMap mWh0,
           const __grid_constant__ CUtensorMap mWh1,
           const float* __restrict__ bz0, const float* __restrict__ bz1,
           const float* __restrict__ br0, const float* __restrict__ br1,
           const float* __restrict__ bh0, const float* __restrict__ bh1,
           const float* Hg, float* OutH)
{
    extern __shared__ __align__(1024) char smem[];
    const uint32_t sb = smem_u32(smem);

    const int tid = threadIdx.x, lane = tid & 31, warp = tid >> 5;
    const int wm = warp & 1, wn = warp >> 1;
    const int mbase = wm * 32, nbase = wn * 32;
    const int lq = lane >> 2, lt = lane & 3;
    const int row0 = (int)(blockIdx.x * 64);

    const CUtensorMap* wmaps[6] = {&mWz0, &mWz1, &mWr0, &mWr1, &mWh0, &mWh1};

    if (tid == 0) {
        mbar_init(sb + 0, 1);
        mbar_init(sb + 8, 1);
        mbar_init(sb + 16, 1);
    }
    __syncthreads();

    auto issueW = [&](int q) {
        const int p = q >> 2, c = q & 3;
        const uint32_t bar = sb + (uint32_t)(q & 1) * 8;
        const uint32_t dst = sb + G_W + (uint32_t)(q & 1) * 16384u;
        mbar_expect(bar, 16384u);
#pragma unroll
        for (int i = 0; i < 4; i++)
            tma2d(dst + i * 4096u, wmaps[p], i * 32, c * 32, bar);
    };

    if (tid == 0) {
        mbar_expect(sb + 16, 65536u);
#pragma unroll
        for (int i = 0; i < 4; i++) {
            tma2d(sb + G_A + i * 8192u, &mA, i * 32, row0, sb + 16);
            tma2d(sb + G_H + i * 8192u, &mH, i * 32, row0, sb + 16);
        }
        issueW(0);
        issueW(1);
    }

    float acc[2][4][4], zreg[2][4][4];
#pragma unroll
    for (int mi = 0; mi < 2; mi++)
#pragma unroll
        for (int j = 0; j < 4; j++)
#pragma unroll
            for (int q = 0; q < 4; q++) acc[mi][j][q] = 0.0f;

    uint32_t bcol0[4], bcol1[4];
#pragma unroll
    for (int j = 0; j < 4; j++) {
        const int n = nbase + j * 8 + lq;
        const uint32_t nb = (uint32_t)((n & 31) * 4);
        bcol0[j] = ((uint32_t)(n >> 5)) * 4096u + (nb ^ ((uint32_t)lt << 4));
        bcol1[j] = ((uint32_t)(n >> 5)) * 4096u + (nb ^ (((uint32_t)(lt + 4)) << 4));
    }

    auto toff = [&](uint32_t region, int r, int c) -> uint32_t {
        return region + (uint32_t)(c >> 5) * 8192u + (uint32_t)r * 128u
               + (((uint32_t)((c & 31) * 4)) ^ ((uint32_t)(r & 7) << 4));
    };

    mbar_wait(sb + 16, 0);

#pragma unroll 1
    for (int q = 0; q < 24; ++q) {
        const int p = q >> 2, c = q & 3;
        mbar_wait(sb + (uint32_t)(q & 1) * 8, (uint32_t)((q >> 1) & 1));
        const uint32_t Areg = (p == 1 || p == 3 || p == 5) ? G_H : G_A;
        const char* Wb = smem + G_W + (uint32_t)(q & 1) * 16384u;

#pragma unroll
        for (int kk = 0; kk < 32; kk += 8) {
            const int kt0 = kk + lt, kt1 = kt0 + 4;
            uint32_t ah[2][4], al[2][4];
#pragma unroll
            for (int mi = 0; mi < 2; mi++) {
                const int r0 = mbase + mi * 16 + lq, r1 = r0 + 8;
                tsplit(*(const float*)(smem + toff(Areg, r0, c * 32 + kt0)), ah[mi][0], al[mi][0]);
                tsplit(*(const float*)(smem + toff(Areg, r1, c * 32 + kt0)), ah[mi][1], al[mi][1]);
                tsplit(*(const float*)(smem + toff(Areg, r0, c * 32 + kt1)), ah[mi][2], al[mi][2]);
                tsplit(*(const float*)(smem + toff(Areg, r1, c * 32 + kt1)), ah[mi][3], al[mi][3]);
            }
#pragma unroll
            for (int j = 0; j < 4; j++) {
                uint32_t bh0, bl0, bh1, bl1;
                tsplit(*(const float*)(Wb + kt0 * 128 + bcol0[j]), bh0, bl0);
                tsplit(*(const float*)(Wb + kt1 * 128 + bcol1[j]), bh1, bl1);
#pragma unroll
                for (int mi = 0; mi < 2; mi++) {
                    mma_tf32(acc[mi][j], ah[mi], bh0, bh1);
                    mma_tf32(acc[mi][j], ah[mi], bl0, bl1);
                    mma_tf32(acc[mi][j], al[mi], bh0, bh1);
                }
            }
        }

        if (q == 7) {
#pragma unroll
            for (int mi = 0; mi < 2; mi++)
#pragma unroll
                for (int j = 0; j < 4; j++)
#pragma unroll
                    for (int qq = 0; qq < 4; qq++) {
                        const int cc = nbase + j * 8 + lt * 2 + (qq & 1);
                        zreg[mi][j][qq] = sigmoidf_(acc[mi][j][qq] + bz0[cc] + bz1[cc]);
                        acc[mi][j][qq] = 0.0f;
                    }
        }
        if (q == 15) {
#pragma unroll
            for (int mi = 0; mi < 2; mi++) {
                const int r0 = mbase + mi * 16 + lq;
#pragma unroll
                for (int j = 0; j < 4; j++)
#pragma unroll
                    for (int qq = 0; qq < 4; qq++) {
                        const int cc = nbase + j * 8 + lt * 2 + (qq & 1);
                        const int rr = (qq < 2) ? r0 : r0 + 8;
                        const float rv = sigmoidf_(acc[mi][j][qq] + br0[cc] + br1[cc]);
                        const float hv = *(const float*)(smem + toff(G_H, rr, cc));
                        acc[mi][j][qq] = rv * hv;
                    }
            }
            __syncthreads();
#pragma unroll
            for (int mi = 0; mi < 2; mi++) {
                const int r0 = mbase + mi * 16 + lq;
#pragma unroll
                for (int j = 0; j < 4; j++)
#pragma unroll
                    for (int qq = 0; qq < 4; qq++) {
                        const int cc = nbase + j * 8 + lt * 2 + (qq & 1);
                        const int rr = (qq < 2) ? r0 : r0 + 8;
                        *(float*)(smem + toff(G_H, rr, cc)) = acc[mi][j][qq];
                        acc[mi][j][qq] = 0.0f;
                    }
            }
        }
        __syncthreads();
        if (q + 2 < 24 && tid == 0) issueW(q + 2);
    }

#pragma unroll
    for (int mi = 0; mi < 2; mi++) {
        const int r0 = mbase + mi * 16 + lq;
        const size_t gr0 = (size_t)row0 + r0, gr1 = gr0 + 8;
#pragma unroll
        for (int j = 0; j < 4; j++) {
            const int col = nbase + j * 8 + lt * 2;
            const float2 h0 = *(const float2*)&Hg[gr0 * 128 + col];
            const float2 h1 = *(const float2*)&Hg[gr1 * 128 + col];
            float o[4];
            const float hv[4] = {h0.x, h0.y, h1.x, h1.y};
#pragma unroll
            for (int qq = 0; qq < 4; qq++) {
                const int cc = col + (qq & 1);
                const float zv = zreg[mi][j][qq];
                o[qq] = fmaxf(acc[mi][j][qq] + bh0[cc] + bh1[cc], 0.0f) * zv
                        + hv[qq] * (1.0f - zv);
            }
            *(float2*)&OutH[gr0 * 128 + col] = make_float2(o[0], o[1]);
            *(float2*)&OutH[gr1 * 128 + col] = make_float2(o[2], o[3]);
        }
    }
}

// ---------------------------------------------------------------------------
// host side
// ---------------------------------------------------------------------------
typedef CUresult (*pfn_encode_t)(CUtensorMap*, CUtensorMapDataType, cuuint32_t,
                                 void*, const cuuint64_t*, const cuuint64_t*,
                                 const cuuint32_t*, const cuuint32_t*,
                                 CUtensorMapInterleave, CUtensorMapSwizzle,
                                 CUtensorMapL2promotion, CUtensorMapFloatOOBfill);
static pfn_encode_t enc_fn = nullptr;

static void map2d(CUtensorMap* m, const void* ptr, uint64_t d0, uint64_t d1,
                  uint32_t b0, uint32_t b1) {
    cuuint64_t dims[2]    = {d0, d1};
    cuuint64_t strides[1] = {d0 * 4};
    cuuint32_t box[2]     = {b0, b1};
    cuuint32_t es[2]      = {1, 1};
    enc_fn(m, CU_TENSOR_MAP_DATA_TYPE_FLOAT32, 2, (void*)ptr, dims, strides, box, es,
           CU_TENSOR_MAP_INTERLEAVE_NONE, CU_TENSOR_MAP_SWIZZLE_128B,
           CU_TENSOR_MAP_L2_PROMOTION_L2_128B, CU_TENSOR_MAP_FLOAT_OOB_FILL_NONE);
}
static void map3d_sup(CUtensorMap* m, const void* ptr) {
    cuuint64_t dims[3]    = {SEQ, SEQ, BATCH};
    cuuint64_t strides[2] = {(uint64_t)SEQ * 4, (uint64_t)SEQ * SEQ * 4};
    cuuint32_t box[3]     = {32, 128, 1};
    cuuint32_t es[3]      = {1, 1, 1};
    enc_fn(m, CU_TENSOR_MAP_DATA_TYPE_FLOAT32, 3, (void*)ptr, dims, strides, box, es,
           CU_TENSOR_MAP_INTERLEAVE_NONE, CU_TENSOR_MAP_SWIZZLE_128B,
           CU_TENSOR_MAP_L2_PROMOTION_L2_128B, CU_TENSOR_MAP_FLOAT_OOB_FILL_NONE);
}

extern "C" void kernel_launch(void* const* d_in, const int* in_sizes, int n_in,
                              void* d_out, int out_size)
{
    const float* x       = (const float*)d_in[0];
    const float* support = (const float*)d_in[1];
    const float* ffd     = (const float*)d_in[2];
    // d_in[3] = mask (unused by reference)
    const float* We  = (const float*)d_in[4];
    const float* be  = (const float*)d_in[5];
    const float* Wz0 = (const float*)d_in[6];
    const float* bz0 = (const float*)d_in[7];
    const float* Wz1 = (const float*)d_in[8];
    const float* bz1 = (const float*)d_in[9];
    const float* Wr0 = (const float*)d_in[10];
    const float* br0 = (const float*)d_in[11];
    const float* Wr1 = (const float*)d_in[12];
    const float* br1 = (const float*)d_in[13];
    const float* Wh0 = (const float*)d_in[14];
    const float* bh0 = (const float*)d_in[15];
    const float* Wh1 = (const float*)d_in[16];
    const float* bh1 = (const float*)d_in[17];

    float *h, *a;
    cudaGetSymbolAddress((void**)&h, g_h);
    cudaGetSymbolAddress((void**)&a, g_a);

    if (!enc_fn) {
        cudaDriverEntryPointQueryResult qr;
        cudaGetDriverEntryPoint("cuTensorMapEncodeTiled", (void**)&enc_fn,
                                cudaEnableDefault, &qr);
    }

    CUtensorMap m_sup, m_x, m_hB, m_a64, m_h64;
    CUtensorMap m_We, m_Wz0, m_Wz1, m_Wr0, m_Wr1, m_Wh0, m_Wh1;
    map3d_sup(&m_sup, support);
    map2d(&m_x,   x, DIM, MTOT, 32, 128);
    map2d(&m_hB,  h, DIM, MTOT, 32, 32);
    map2d(&m_a64, a, DIM, MTOT, 32, 64);
    map2d(&m_h64, h, DIM, MTOT, 32, 64);
    map2d(&m_We,  We,  DIM, DIM, 32, 32);
    map2d(&m_Wz0, Wz0, DIM, DIM, 32, 32);
    map2d(&m_Wz1, Wz1, DIM, DIM, 32, 32);
    map2d(&m_Wr0, Wr0, DIM, DIM, 32, 32);
    map2d(&m_Wr1, Wr1, DIM, DIM, 32, 32);
    map2d(&m_Wh0, Wh0, DIM, DIM, 32, 32);
    map2d(&m_Wh1, Wh1, DIM, DIM, 32, 32);

    cudaFuncSetAttribute(encode_tma,  cudaFuncAttributeMaxDynamicSharedMemorySize, SMEM_BYTES);
    cudaFuncSetAttribute(spmm_tma64,  cudaFuncAttributeMaxDynamicSharedMemorySize, S64_SMEM);
    cudaFuncSetAttribute(fused_gate,  cudaFuncAttributeMaxDynamicSharedMemorySize, G_SMEM);

    const dim3 grd_enc(MTOT / 128);            // 256
    const dim3 grd_spmm(SEQ / 128 * 2, BATCH); // (32,16) = 512
    const dim3 grd_fused(MTOT / 64);           // 512

    // h = relu(x @ We + be)
    encode_tma<<<grd_enc, 256, SMEM_BYTES>>>(m_x, m_We, be, h);

    for (int t = 0; t < 2; ++t) {
        // a = (support @ h) * (1 + FFD)
        spmm_tma64<<<grd_spmm, 256, S64_SMEM>>>(m_sup, m_hB, ffd, a);
        // fused gates + GRU combine
        float* dst = (t == 1) ? (float*)d_out : h;
        fused_gate<<<grd_fused, 256, G_SMEM>>>(m_a64, m_h64,
                                               m_Wz0, m_Wz1, m_Wr0, m_Wr1, m_Wh0, m_Wh1,
                                               bz0, bz1, br0, br1, bh0, bh1, h, dst);
    }
}

// round 13
// speedup vs baseline: 1.0059x; 1.0059x over previous
#include <cuda_runtime.h>
#include <cuda.h>
#include <math.h>
#include <stdint.h>

#define BATCH 16
#define SEQ   2048
#define DIM   128
#define MTOT  (BATCH * SEQ)

// ---------------- scratch (allocation-free device globals) ----------------
__device__ float  g_h [MTOT * DIM];
__device__ float  g_a [MTOT * DIM];
__device__ float2 g_hs[MTOT * DIM];   // h pre-split {tf32_hi, lo}, row-major [row][256 floats]

__device__ __forceinline__ float sigmoidf_(float v) {
    return 1.0f / (1.0f + __expf(-v));
}
__device__ __forceinline__ uint32_t smem_u32(const void* p) {
    uint32_t a;
    asm("{ .reg .u64 t; cvta.to.shared.u64 t, %1; cvt.u32.u64 %0, t; }" : "=r"(a) : "l"(p));
    return a;
}
// truncation split: hi = top tf32 bits, lo = exact remainder (2 ops).
__device__ __forceinline__ void tsplit(float x, uint32_t& hi, uint32_t& lo) {
    hi = __float_as_uint(x) & 0xFFFFE000u;
    lo = __float_as_uint(x - __uint_as_float(hi));
}
__device__ __forceinline__ float2 split2f(float x) {
    uint32_t hi, lo;
    tsplit(x, hi, lo);
    return make_float2(__uint_as_float(hi), __uint_as_float(lo));
}
__device__ __forceinline__ void mma_tf32(float* d, const uint32_t* a,
                                         uint32_t b0, uint32_t b1) {
    asm volatile("mma.sync.aligned.m16n8k8.row.col.f32.tf32.tf32.f32 "
                 "{%0,%1,%2,%3}, {%4,%5,%6,%7}, {%8,%9}, {%0,%1,%2,%3};"
                 : "+f"(d[0]), "+f"(d[1]), "+f"(d[2]), "+f"(d[3])
                 : "r"(a[0]), "r"(a[1]), "r"(a[2]), "r"(a[3]), "r"(b0), "r"(b1));
}
// ---- TMA + mbarrier ----
__device__ __forceinline__ void tma2d(uint32_t dst, const void* map,
                                      int c0, int c1, uint32_t mbar) {
    asm volatile("cp.async.bulk.tensor.2d.shared::cta.global.tile.mbarrier::complete_tx::bytes "
                 "[%0], [%1, {%2, %3}], [%4];"
                 :: "r"(dst), "l"(map), "r"(c0), "r"(c1), "r"(mbar) : "memory");
}
__device__ __forceinline__ void tma3d(uint32_t dst, const void* map,
                                      int c0, int c1, int c2, uint32_t mbar) {
    asm volatile("cp.async.bulk.tensor.3d.shared::cta.global.tile.mbarrier::complete_tx::bytes "
                 "[%0], [%1, {%2, %3, %4}], [%5];"
                 :: "r"(dst), "l"(map), "r"(c0), "r"(c1), "r"(c2), "r"(mbar) : "memory");
}
__device__ __forceinline__ void mbar_init(uint32_t mbar, uint32_t cnt) {
    asm volatile("mbarrier.init.shared.b64 [%0], %1;" :: "r"(mbar), "r"(cnt) : "memory");
}
__device__ __forceinline__ void mbar_expect(uint32_t mbar, uint32_t bytes) {
    asm volatile("mbarrier.arrive.expect_tx.shared.b64 _, [%0], %1;"
                 :: "r"(mbar), "r"(bytes) : "memory");
}
__device__ __forceinline__ void mbar_wait(uint32_t mbar, uint32_t parity) {
    uint32_t done;
    asm volatile("{\n\t.reg .pred p;\n\t"
                 "mbarrier.try_wait.parity.acquire.cta.shared::cta.b64 p, [%1], %2;\n\t"
                 "selp.b32 %0, 1, 0, p;\n\t}"
                 : "=r"(done) : "r"(mbar), "r"(parity) : "memory");
    while (!done) {
        asm volatile("{\n\t.reg .pred p;\n\t"
                     "mbarrier.try_wait.parity.acquire.cta.shared::cta.b64 p, [%1], %2;\n\t"
                     "selp.b32 %0, 1, 0, p;\n\t}"
                     : "=r"(done) : "r"(mbar), "r"(parity) : "memory");
    }
}

// ===========================================================================
// Kernel 1a: encode (r9 structure; epilogue also writes pre-split hs)
// ===========================================================================
#define E_NSTAGE  3
#define E_STAGE   32768u
#define E_SMEM    (1024u + E_NSTAGE * E_STAGE)

__global__ void __launch_bounds__(256, 2)
encode_tma(const __grid_constant__ CUtensorMap mA1,
           const __grid_constant__ CUtensorMap mB1,
           const float* __restrict__ bias1, float* __restrict__ Cout,
           float2* __restrict__ OutHS)
{
    extern __shared__ __align__(1024) char smem[];
    const uint32_t sb = smem_u32(smem);

    const int tid = threadIdx.x, lane = tid & 31, warp = tid >> 5;
    const int wm = warp & 3, wn = warp >> 2;
    const int mbase = wm * 32, nbase = wn * 64;
    const int lq = lane >> 2, lt = lane & 3;
    const size_t rowTile = (size_t)blockIdx.x * 128;
    constexpr int NC = 4;

    if (tid == 0) {
#pragma unroll
        for (int s = 0; s < E_NSTAGE; s++) mbar_init(sb + s * 8, 1);
    }
    __syncthreads();

    auto issue = [&](int c) {
        const int s = c % E_NSTAGE;
        const uint32_t bar  = sb + s * 8;
        const uint32_t dstA = sb + 1024u + s * E_STAGE;
        const uint32_t dstB = dstA + 16384u;
        const int k0 = c * 32;
        mbar_expect(bar, E_STAGE);
        tma2d(dstA, &mA1, k0, (int)(blockIdx.x * 128), bar);
#pragma unroll
        for (int i = 0; i < 4; i++)
            tma2d(dstB + i * 4096u, &mB1, i * 32, k0, bar);
    };

    float acc[2][8][4];
#pragma unroll
    for (int mi = 0; mi < 2; mi++)
#pragma unroll
        for (int j = 0; j < 8; j++)
#pragma unroll
            for (int q = 0; q < 4; q++) acc[mi][j][q] = 0.0f;

    const uint32_t aswz = (uint32_t)lq << 4;
    uint32_t bcol0[8], bcol1[8];
#pragma unroll
    for (int j = 0; j < 8; j++) {
        const int n  = nbase + j * 8 + lq;
        const uint32_t nb = (uint32_t)((n & 31) * 4);
        bcol0[j] = ((uint32_t)(n >> 5)) * 4096u + (nb ^ ((uint32_t)lt << 4));
        bcol1[j] = ((uint32_t)(n >> 5)) * 4096u + (nb ^ (((uint32_t)(lt + 4)) << 4));
    }

    if (tid == 0) { issue(0); issue(1); issue(2); }

#pragma unroll 1
    for (int c = 0; c < NC; ++c) {
        const int s = c % E_NSTAGE;
        mbar_wait(sb + s * 8, (uint32_t)((c / E_NSTAGE) & 1));
        const char* As = smem + 1024u + s * E_STAGE;
        const char* Bs = As + 16384;

#pragma unroll
        for (int kk = 0; kk < 32; kk += 8) {
            const int kt0 = kk + lt, kt1 = kt0 + 4;
            uint32_t ah[2][4], al[2][4];
#pragma unroll
            for (int mi = 0; mi < 2; mi++) {
                const int r0 = mbase + mi * 16 + lq, r1 = r0 + 8;
                const uint32_t c0 = ((uint32_t)(kt0 * 4)) ^ aswz;
                const uint32_t c1 = ((uint32_t)(kt1 * 4)) ^ aswz;
                tsplit(*(const float*)(As + r0 * 128 + c0), ah[mi][0], al[mi][0]);
                tsplit(*(const float*)(As + r1 * 128 + c0), ah[mi][1], al[mi][1]);
                tsplit(*(const float*)(As + r0 * 128 + c1), ah[mi][2], al[mi][2]);
                tsplit(*(const float*)(As + r1 * 128 + c1), ah[mi][3], al[mi][3]);
            }
#pragma unroll
            for (int j = 0; j < 8; j++) {
                uint32_t bh0, bl0, bh1, bl1;
                tsplit(*(const float*)(Bs + kt0 * 128 + bcol0[j]), bh0, bl0);
                tsplit(*(const float*)(Bs + kt1 * 128 + bcol1[j]), bh1, bl1);
#pragma unroll
                for (int mi = 0; mi < 2; mi++) {
                    mma_tf32(acc[mi][j], ah[mi], bh0, bh1);
                    mma_tf32(acc[mi][j], ah[mi], bl0, bl1);
                    mma_tf32(acc[mi][j], al[mi], bh0, bh1);
                }
            }
        }
        __syncthreads();
        if (c + E_NSTAGE < NC && tid == 0) issue(c + E_NSTAGE);
    }

#pragma unroll
    for (int mi = 0; mi < 2; mi++) {
        const int rA = mbase + mi * 16 + lq;
        const size_t gr0 = rowTile + rA, gr1 = gr0 + 8;
#pragma unroll
        for (int j = 0; j < 8; j++) {
            const int col = nbase + j * 8 + lt * 2;
            float o[4];
#pragma unroll
            for (int q = 0; q < 4; q++) {
                const int cc = col + (q & 1);
                o[q] = fmaxf(acc[mi][j][q] + bias1[cc], 0.0f);
            }
            *(float2*)&Cout[gr0 * 128 + col] = make_float2(o[0], o[1]);
            *(float2*)&Cout[gr1 * 128 + col] = make_float2(o[2], o[3]);
            OutHS[gr0 * 128 + col]     = split2f(o[0]);
            OutHS[gr0 * 128 + col + 1] = split2f(o[1]);
            OutHS[gr1 * 128 + col]     = split2f(o[2]);
            OutHS[gr1 * 128 + col + 1] = split2f(o[3]);
        }
    }
}

// ===========================================================================
// Kernel 1b: spmm v4 — 128x128 tile (r9 geometry), B pre-split (zero B ALU),
// 2-stage 48KB pipeline, 2 CTAs/SM.
// ===========================================================================
#define SP_STAGE 49152u
#define SP_SMEM  (1024u + 2u * SP_STAGE)   // 99328

__global__ void __launch_bounds__(256, 2)
spmm_ps(const __grid_constant__ CUtensorMap mA1,
        const __grid_constant__ CUtensorMap mHs,
        const float* __restrict__ ffd, float* __restrict__ Cout)
{
    extern __shared__ __align__(1024) char smem[];
    const uint32_t sb = smem_u32(smem);

    const int tid = threadIdx.x, lane = tid & 31, warp = tid >> 5;
    const int wm = warp & 3, wn = warp >> 2;
    const int mbase = wm * 32, nbase = wn * 64;
    const int lq = lane >> 2, lt = lane & 3;
    const int b = (int)blockIdx.y;
    const size_t rowTile = (size_t)b * SEQ + (size_t)blockIdx.x * 128;
    constexpr int NC = SEQ / 32;   // 64

    if (tid == 0) { mbar_init(sb + 0, 1); mbar_init(sb + 8, 1); }
    __syncthreads();

    auto issue = [&](int c) {
        const int s = c & 1;
        const uint32_t bar  = sb + s * 8;
        const uint32_t dstA = sb + 1024u + s * SP_STAGE;
        const uint32_t dstB = dstA + 16384u;
        const int k0 = c * 32;
        mbar_expect(bar, SP_STAGE);
        tma3d(dstA, &mA1, k0, (int)(blockIdx.x * 128), b, bar);
        const int brow = b * SEQ + k0;
#pragma unroll
        for (int i = 0; i < 8; i++)
            tma2d(dstB + i * 4096u, &mHs, i * 32, brow, bar);
    };

    float acc[2][8][4];
#pragma unroll
    for (int mi = 0; mi < 2; mi++)
#pragma unroll
        for (int j = 0; j < 8; j++)
#pragma unroll
            for (int q = 0; q < 4; q++) acc[mi][j][q] = 0.0f;

    const uint32_t aswz = (uint32_t)lq << 4;
    uint32_t bp0[8], bp1[8];
#pragma unroll
    for (int j = 0; j < 8; j++) {
        const int f  = 2 * (nbase + j * 8 + lq);       // split-pair base float index
        const uint32_t fb = (uint32_t)((f & 31) * 4);
        bp0[j] = ((uint32_t)(f >> 5)) * 4096u + (fb ^ ((uint32_t)lt << 4));
        bp1[j] = ((uint32_t)(f >> 5)) * 4096u + (fb ^ (((uint32_t)(lt + 4)) << 4));
    }

    if (tid == 0) { issue(0); issue(1); }

#pragma unroll 1
    for (int c = 0; c < NC; ++c) {
        const int s = c & 1;
        mbar_wait(sb + s * 8, (uint32_t)((c >> 1) & 1));
        const char* As = smem + 1024u + s * SP_STAGE;
        const char* Bs = As + 16384;

#pragma unroll
        for (int kk = 0; kk < 32; kk += 8) {
            const int kt0 = kk + lt, kt1 = kt0 + 4;
            uint32_t ah[2][4], al[2][4];
#pragma unroll
            for (int mi = 0; mi < 2; mi++) {
                const int r0 = mbase + mi * 16 + lq, r1 = r0 + 8;
                const uint32_t c0 = ((uint32_t)(kt0 * 4)) ^ aswz;
                const uint32_t c1 = ((uint32_t)(kt1 * 4)) ^ aswz;
                tsplit(*(const float*)(As + r0 * 128 + c0), ah[mi][0], al[mi][0]);
                tsplit(*(const float*)(As + r1 * 128 + c0), ah[mi][1], al[mi][1]);
                tsplit(*(const float*)(As + r0 * 128 + c1), ah[mi][2], al[mi][2]);
                tsplit(*(const float*)(As + r1 * 128 + c1), ah[mi][3], al[mi][3]);
            }
#pragma unroll
            for (int j = 0; j < 8; j++) {
                const uint2 q0 = *(const uint2*)(Bs + kt0 * 128 + bp0[j]);
                const uint2 q1 = *(const uint2*)(Bs + kt1 * 128 + bp1[j]);
#pragma unroll
                for (int mi = 0; mi < 2; mi++) {
                    mma_tf32(acc[mi][j], ah[mi], q0.x, q1.x);   // hi*hi
                    mma_tf32(acc[mi][j], ah[mi], q0.y, q1.y);   // hi*lo
                    mma_tf32(acc[mi][j], al[mi], q0.x, q1.x);   // lo*hi
                }
            }
        }
        __syncthreads();
        if (c + 2 < NC && tid == 0) issue(c + 2);
    }

#pragma unroll
    for (int mi = 0; mi < 2; mi++) {
        const int rA = mbase + mi * 16 + lq;
        const size_t gr0 = rowTile + rA, gr1 = gr0 + 8;
        const float s0 = 1.0f + ffd[gr0];
        const float s1 = 1.0f + ffd[gr1];
#pragma unroll
        for (int j = 0; j < 8; j++) {
            const int col = nbase + j * 8 + lt * 2;
            *(float2*)&Cout[gr0 * 128 + col] = make_float2(acc[mi][j][0] * s0, acc[mi][j][1] * s0);
            *(float2*)&Cout[gr1 * 128 + col] = make_float2(acc[mi][j][2] * s1, acc[mi][j][3] * s1);
        }
    }
}

// ===========================================================================
// Kernel 2: fused GRU gates v4 — 64-row tile, interleaved (Wz|Wr) pairs with
// A-fragment reuse, 3-slot weight ring (2 CTAs/SM), race-fixed ro writeback.
// Weight stream g=0..23: g<16: pair p=g/2 (p<4: a@{Wz0,Wr0}; p>=4: h@{Wz1,Wr1});
// g 16..19: Wh0(a); g 20..23: Wh1(ro).
// ===========================================================================
#define G_A    1024u
#define G_H    (G_A + 32768u)
#define G_W    (G_H + 32768u)
#define G_SMEM (G_W + 3u * 16384u)    // 115712 (<= 116736 for 2 CTAs/SM)
#define G_BAR_AH (G_A - 32u)          // a/h tile barrier at sb+992

__global__ void __launch_bounds__(256, 2)
fused_gate(const __grid_constant__ CUtensorMap mA,
           const __grid_constant__ CUtensorMap mH,
           const __grid_constant__ CUtensorMap mWz0,
           const __grid_constant__ CUtensorMap mWz1,
           const __grid_constant__ CUtensorMap mWr0,
           const __grid_constant__ CUtensorMap mWr1,
           const __grid_constant__ CUtensorMap mWh0,
           const __grid_constant__ CUtensorMap mWh1,
           const float* __restrict__ bz0, const float* __restrict__ bz1,
           const float* __restrict__ br0, const float* __restrict__ br1,
           const float* __restrict__ bh0, const float* __restrict__ bh1,
           const float* Hg, float* OutH, float2* OutHS)
{
    extern __shared__ __align__(1024) char smem[];
    const uint32_t sb = smem_u32(smem);

    const int tid = threadIdx.x, lane = tid & 31, warp = tid >> 5;
    const int wm = warp & 1, wn = warp >> 1;
    const int mbase = wm * 32, nbase = wn * 32;
    const int lq = lane >> 2, lt = lane & 3;
    const int row0 = (int)(blockIdx.x * 64);

    if (tid == 0) {
        mbar_init(sb + 0, 1);
        mbar_init(sb + 8, 1);
        mbar_init(sb + 16, 1);
        mbar_init(sb + G_BAR_AH, 1);
    }
    __syncthreads();

    auto issueW = [&](int g) {
        const CUtensorMap* mp;
        int c;
        if (g < 16) {
            const int p = g >> 1;
            c = p & 3;
            mp = (g & 1) ? ((p < 4) ? &mWr0 : &mWr1)
                         : ((p < 4) ? &mWz0 : &mWz1);
        } else {
            c = g & 3;
            mp = (g < 20) ? &mWh0 : &mWh1;
        }
        const uint32_t bar = sb + (uint32_t)(g % 3) * 8;
        const uint32_t dst = sb + G_W + (uint32_t)(g % 3) * 16384u;
        mbar_expect(bar, 16384u);
#pragma unroll
        for (int i = 0; i < 4; i++)
            tma2d(dst + i * 4096u, mp, i * 32, c * 32, bar);
    };

    if (tid == 0) {
        mbar_expect(sb + G_BAR_AH, 65536u);
#pragma unroll
        for (int i = 0; i < 4; i++) {
            tma2d(sb + G_A + i * 8192u, &mA, i * 32, row0, sb + G_BAR_AH);
            tma2d(sb + G_H + i * 8192u, &mH, i * 32, row0, sb + G_BAR_AH);
        }
        issueW(0); issueW(1); issueW(2);
    }

    float acc_z[2][4][4], acc_r[2][4][4];
#pragma unroll
    for (int mi = 0; mi < 2; mi++)
#pragma unroll
        for (int j = 0; j < 4; j++)
#pragma unroll
            for (int q = 0; q < 4; q++) { acc_z[mi][j][q] = 0.0f; acc_r[mi][j][q] = 0.0f; }

    uint32_t bcol0[4], bcol1[4];
#pragma unroll
    for (int j = 0; j < 4; j++) {
        const int n = nbase + j * 8 + lq;
        const uint32_t nb = (uint32_t)((n & 31) * 4);
        bcol0[j] = ((uint32_t)(n >> 5)) * 4096u + (nb ^ ((uint32_t)lt << 4));
        bcol1[j] = ((uint32_t)(n >> 5)) * 4096u + (nb ^ (((uint32_t)(lt + 4)) << 4));
    }

    // byte offset of element (row r, col c) in a 64-row tile region
    auto toff = [&](uint32_t region, int r, int c) -> uint32_t {
        return region + (uint32_t)(c >> 5) * 8192u + (uint32_t)r * 128u
               + (((uint32_t)((c & 31) * 4)) ^ ((uint32_t)(r & 7) << 4));
    };

    mbar_wait(sb + G_BAR_AH, 0);   // a & h tiles resident

    // ---- dual-gate phase: 8 pairs ----
#pragma unroll 1
    for (int p = 0; p < 8; ++p) {
        const int g0 = 2 * p, g1 = 2 * p + 1;
        mbar_wait(sb + (uint32_t)(g0 % 3) * 8, (uint32_t)((g0 / 3) & 1));
        mbar_wait(sb + (uint32_t)(g1 % 3) * 8, (uint32_t)((g1 / 3) & 1));
        const int c = p & 3;
        const uint32_t Areg = (p < 4) ? G_A : G_H;
        const char* Wz = smem + G_W + (uint32_t)(g0 % 3) * 16384u;
        const char* Wr = smem + G_W + (uint32_t)(g1 % 3) * 16384u;

#pragma unroll
        for (int kk = 0; kk < 32; kk += 8) {
            const int kt0 = kk + lt, kt1 = kt0 + 4;
            uint32_t ah[2][4], al[2][4];
#pragma unroll
            for (int mi = 0; mi < 2; mi++) {
                const int r0 = mbase + mi * 16 + lq, r1 = r0 + 8;
                tsplit(*(const float*)(smem + toff(Areg, r0, c * 32 + kt0)), ah[mi][0], al[mi][0]);
                tsplit(*(const float*)(smem + toff(Areg, r1, c * 32 + kt0)), ah[mi][1], al[mi][1]);
                tsplit(*(const float*)(smem + toff(Areg, r0, c * 32 + kt1)), ah[mi][2], al[mi][2]);
                tsplit(*(const float*)(smem + toff(Areg, r1, c * 32 + kt1)), ah[mi][3], al[mi][3]);
            }
#pragma unroll
            for (int j = 0; j < 4; j++) {
                uint32_t bh0, bl0, bh1, bl1;
                tsplit(*(const float*)(Wz + kt0 * 128 + bcol0[j]), bh0, bl0);
                tsplit(*(const float*)(Wz + kt1 * 128 + bcol1[j]), bh1, bl1);
#pragma unroll
                for (int mi = 0; mi < 2; mi++) {
                    mma_tf32(acc_z[mi][j], ah[mi], bh0, bh1);
                    mma_tf32(acc_z[mi][j], ah[mi], bl0, bl1);
                    mma_tf32(acc_z[mi][j], al[mi], bh0, bh1);
                }
                tsplit(*(const float*)(Wr + kt0 * 128 + bcol0[j]), bh0, bl0);
                tsplit(*(const float*)(Wr + kt1 * 128 + bcol1[j]), bh1, bl1);
#pragma unroll
                for (int mi = 0; mi < 2; mi++) {
                    mma_tf32(acc_r[mi][j], ah[mi], bh0, bh1);
                    mma_tf32(acc_r[mi][j], ah[mi], bl0, bl1);
                    mma_tf32(acc_r[mi][j], al[mi], bh0, bh1);
                }
            }
        }

        if (p == 7) {
            // z = sigmoid(acc_z + bz) kept in acc_z; ro = sigmoid(acc_r+br)*h
            // computed into acc_r (H reads), barrier, overwrite H, reset acc_r.
#pragma unroll
            for (int mi = 0; mi < 2; mi++) {
                const int r0 = mbase + mi * 16 + lq;
#pragma unroll
                for (int j = 0; j < 4; j++)
#pragma unroll
                    for (int qq = 0; qq < 4; qq++) {
                        const int cc = nbase + j * 8 + lt * 2 + (qq & 1);
                        const int rr = (qq < 2) ? r0 : r0 + 8;
                        acc_z[mi][j][qq] = sigmoidf_(acc_z[mi][j][qq] + bz0[cc] + bz1[cc]);
                        const float rv = sigmoidf_(acc_r[mi][j][qq] + br0[cc] + br1[cc]);
                        acc_r[mi][j][qq] = rv * *(const float*)(smem + toff(G_H, rr, cc));
                    }
            }
            __syncthreads();     // all warps done READING H
#pragma unroll
            for (int mi = 0; mi < 2; mi++) {
                const int r0 = mbase + mi * 16 + lq;
#pragma unroll
                for (int j = 0; j < 4; j++)
#pragma unroll
                    for (int qq = 0; qq < 4; qq++) {
                        const int cc = nbase + j * 8 + lt * 2 + (qq & 1);
                        const int rr = (qq < 2) ? r0 : r0 + 8;
                        *(float*)(smem + toff(G_H, rr, cc)) = acc_r[mi][j][qq];
                        acc_r[mi][j][qq] = 0.0f;
                    }
            }
        }
        __syncthreads();
        if (tid == 0) {
            if (2 * p + 3 < 24) issueW(2 * p + 3);
            if (2 * p + 4 < 24) issueW(2 * p + 4);
        }
    }

    // ---- single-gate phase: Wh0(a) g=16..19, Wh1(ro) g=20..23 -> acc_r ----
#pragma unroll 1
    for (int g = 16; g < 24; ++g) {
        mbar_wait(sb + (uint32_t)(g % 3) * 8, (uint32_t)((g / 3) & 1));
        const int c = g & 3;
        const uint32_t Areg = (g < 20) ? G_A : G_H;
        const char* Wb = smem + G_W + (uint32_t)(g % 3) * 16384u;

#pragma unroll
        for (int kk = 0; kk < 32; kk += 8) {
            const int kt0 = kk + lt, kt1 = kt0 + 4;
            uint32_t ah[2][4], al[2][4];
#pragma unroll
            for (int mi = 0; mi < 2; mi++) {
                const int r0 = mbase + mi * 16 + lq, r1 = r0 + 8;
                tsplit(*(const float*)(smem + toff(Areg, r0, c * 32 + kt0)), ah[mi][0], al[mi][0]);
                tsplit(*(const float*)(smem + toff(Areg, r1, c * 32 + kt0)), ah[mi][1], al[mi][1]);
                tsplit(*(const float*)(smem + toff(Areg, r0, c * 32 + kt1)), ah[mi][2], al[mi][2]);
                tsplit(*(const float*)(smem + toff(Areg, r1, c * 32 + kt1)), ah[mi][3], al[mi][3]);
            }
#pragma unroll
            for (int j = 0; j < 4; j++) {
                uint32_t bh0, bl0, bh1, bl1;
                tsplit(*(const float*)(Wb + kt0 * 128 + bcol0[j]), bh0, bl0);
                tsplit(*(const float*)(Wb + kt1 * 128 + bcol1[j]), bh1, bl1);
#pragma unroll
                for (int mi = 0; mi < 2; mi++) {
                    mma_tf32(acc_r[mi][j], ah[mi], bh0, bh1);
                    mma_tf32(acc_r[mi][j], ah[mi], bl0, bl1);
                    mma_tf32(acc_r[mi][j], al[mi], bh0, bh1);
                }
            }
        }
        __syncthreads();
        if (tid == 0 && g + 3 < 24) issueW(g + 3);
    }

    // epilogue: h' = relu(acc_r + bh)*z + h_gmem*(1-z);  z lives in acc_z
#pragma unroll
    for (int mi = 0; mi < 2; mi++) {
        const int r0 = mbase + mi * 16 + lq;
        const size_t gr0 = (size_t)row0 + r0, gr1 = gr0 + 8;
#pragma unroll
        for (int j = 0; j < 4; j++) {
            const int col = nbase + j * 8 + lt * 2;
            const float2 h0 = *(const float2*)&Hg[gr0 * 128 + col];
            const float2 h1 = *(const float2*)&Hg[gr1 * 128 + col];
            float o[4];
            const float hv[4] = {h0.x, h0.y, h1.x, h1.y};
#pragma unroll
            for (int qq = 0; qq < 4; qq++) {
                const int cc = col + (qq & 1);
                const float zv = acc_z[mi][j][qq];
                o[qq] = fmaxf(acc_r[mi][j][qq] + bh0[cc] + bh1[cc], 0.0f) * zv
                        + hv[qq] * (1.0f - zv);
            }
            *(float2*)&OutH[gr0 * 128 + col] = make_float2(o[0], o[1]);
            *(float2*)&OutH[gr1 * 128 + col] = make_float2(o[2], o[3]);
            if (OutHS) {
                OutHS[gr0 * 128 + col]     = split2f(o[0]);
                OutHS[gr0 * 128 + col + 1] = split2f(o[1]);
                OutHS[gr1 * 128 + col]     = split2f(o[2]);
                OutHS[gr1 * 128 + col + 1] = split2f(o[3]);
            }
        }
    }
}

// ---------------------------------------------------------------------------
// host side
// ---------------------------------------------------------------------------
typedef CUresult (*pfn_encode_t)(CUtensorMap*, CUtensorMapDataType, cuuint32_t,
                                 void*, const cuuint64_t*, const cuuint64_t*,
                                 const cuuint32_t*, const cuuint32_t*,
                                 CUtensorMapInterleave, CUtensorMapSwizzle,
                                 CUtensorMapL2promotion, CUtensorMapFloatOOBfill);
static pfn_encode_t enc_fn = nullptr;

static void map2d(CUtensorMap* m, const void* ptr, uint64_t d0, uint64_t d1,
                  uint32_t b0, uint32_t b1) {
    cuuint64_t dims[2]    = {d0, d1};
    cuuint64_t strides[1] = {d0 * 4};
    cuuint32_t box[2]     = {b0, b1};
    cuuint32_t es[2]      = {1, 1};
    enc_fn(m, CU_TENSOR_MAP_DATA_TYPE_FLOAT32, 2, (void*)ptr, dims, strides, box, es,
           CU_TENSOR_MAP_INTERLEAVE_NONE, CU_TENSOR_MAP_SWIZZLE_128B,
           CU_TENSOR_MAP_L2_PROMOTION_L2_128B, CU_TENSOR_MAP_FLOAT_OOB_FILL_NONE);
}
static void map3d_sup(CUtensorMap* m, const void* ptr) {
    cuuint64_t dims[3]    = {SEQ, SEQ, BATCH};
    cuuint64_t strides[2] = {(uint64_t)SEQ * 4, (uint64_t)SEQ * SEQ * 4};
    cuuint32_t box[3]     = {32, 128, 1};
    cuuint32_t es[3]      = {1, 1, 1};
    enc_fn(m, CU_TENSOR_MAP_DATA_TYPE_FLOAT32, 3, (void*)ptr, dims, strides, box, es,
           CU_TENSOR_MAP_INTERLEAVE_NONE, CU_TENSOR_MAP_SWIZZLE_128B,
           CU_TENSOR_MAP_L2_PROMOTION_L2_128B, CU_TENSOR_MAP_FLOAT_OOB_FILL_NONE);
}

extern "C" void kernel_launch(void* const* d_in, const int* in_sizes, int n_in,
                              void* d_out, int out_size)
{
    const float* x       = (const float*)d_in[0];
    const float* support = (const float*)d_in[1];
    const float* ffd     = (const float*)d_in[2];
    // d_in[3] = mask (unused by reference)
    const float* We  = (const float*)d_in[4];
    const float* be  = (const float*)d_in[5];
    const float* Wz0 = (const float*)d_in[6];
    const float* bz0 = (const float*)d_in[7];
    const float* Wz1 = (const float*)d_in[8];
    const float* bz1 = (const float*)d_in[9];
    const float* Wr0 = (const float*)d_in[10];
    const float* br0 = (const float*)d_in[11];
    const float* Wr1 = (const float*)d_in[12];
    const float* br1 = (const float*)d_in[13];
    const float* Wh0 = (const float*)d_in[14];
    const float* bh0 = (const float*)d_in[15];
    const float* Wh1 = (const float*)d_in[16];
    const float* bh1 = (const float*)d_in[17];

    float *h, *a;
    float2* hs;
    cudaGetSymbolAddress((void**)&h,  g_h);
    cudaGetSymbolAddress((void**)&a,  g_a);
    cudaGetSymbolAddress((void**)&hs, g_hs);

    if (!enc_fn) {
        cudaDriverEntryPointQueryResult qr;
        cudaGetDriverEntryPoint("cuTensorMapEncodeTiled", (void**)&enc_fn,
                                cudaEnableDefault, &qr);
    }

    CUtensorMap m_sup, m_x, m_hs, m_a64, m_h64;
    CUtensorMap m_We, m_Wz0, m_Wz1, m_Wr0, m_Wr1, m_Wh0, m_Wh1;
    map3d_sup(&m_sup, support);
    map2d(&m_x,   x,  DIM,     MTOT, 32, 128);
    map2d(&m_hs,  hs, DIM * 2, MTOT, 32, 32);
    map2d(&m_a64, a,  DIM,     MTOT, 32, 64);
    map2d(&m_h64, h,  DIM,     MTOT, 32, 64);
    map2d(&m_We,  We,  DIM, DIM, 32, 32);
    map2d(&m_Wz0, Wz0, DIM, DIM, 32, 32);
    map2d(&m_Wz1, Wz1, DIM, DIM, 32, 32);
    map2d(&m_Wr0, Wr0, DIM, DIM, 32, 32);
    map2d(&m_Wr1, Wr1, DIM, DIM, 32, 32);
    map2d(&m_Wh0, Wh0, DIM, DIM, 32, 32);
    map2d(&m_Wh1, Wh1, DIM, DIM, 32, 32);

    cudaFuncSetAttribute(encode_tma, cudaFuncAttributeMaxDynamicSharedMemorySize, E_SMEM);
    cudaFuncSetAttribute(spmm_ps,    cudaFuncAttributeMaxDynamicSharedMemorySize, SP_SMEM);
    cudaFuncSetAttribute(fused_gate, cudaFuncAttributeMaxDynamicSharedMemorySize, G_SMEM);

    const dim3 grd_enc(MTOT / 128);            // 256
    const dim3 grd_spmm(SEQ / 128, BATCH);     // (16,16)
    const dim3 grd_fused(MTOT / 64);           // 512

    // h = relu(x @ We + be); also hs = split(h)
    encode_tma<<<grd_enc, 256, E_SMEM>>>(m_x, m_We, be, h, hs);

    for (int t = 0; t < 2; ++t) {
        // a = (support @ h) * (1 + FFD)   [B pre-split]
        spmm_ps<<<grd_spmm, 256, SP_SMEM>>>(m_sup, m_hs, ffd, a);
        // fused gates + GRU combine
        float*  dst  = (t == 1) ? (float*)d_out : h;
        float2* dsts = (t == 1) ? nullptr : hs;
        fused_gate<<<grd_fused, 256, G_SMEM>>>(m_a64, m_h64,
                                               m_Wz0, m_Wz1, m_Wr0, m_Wr1, m_Wh0, m_Wh1,
                                               bz0, bz1, br0, br1, bh0, bh1, h, dst, dsts);
    }
}

// round 14
// speedup vs baseline: 1.0230x; 1.0170x over previous
#include <cuda_runtime.h>
#include <cuda.h>
#include <math.h>
#include <stdint.h>

#define BATCH 16
#define SEQ   2048
#define DIM   128
#define MTOT  (BATCH * SEQ)

// ---------------- scratch (allocation-free device globals) ----------------
__device__ float g_h[MTOT * DIM];
__device__ float g_a[MTOT * DIM];

__device__ __forceinline__ float sigmoidf_(float v) {
    return 1.0f / (1.0f + __expf(-v));
}
__device__ __forceinline__ uint32_t smem_u32(const void* p) {
    uint32_t a;
    asm("{ .reg .u64 t; cvta.to.shared.u64 t, %1; cvt.u32.u64 %0, t; }" : "=r"(a) : "l"(p));
    return a;
}
// truncation split: hi = top tf32 bits, lo = exact remainder (2 ops).
__device__ __forceinline__ void tsplit(float x, uint32_t& hi, uint32_t& lo) {
    hi = __float_as_uint(x) & 0xFFFFE000u;
    lo = __float_as_uint(x - __uint_as_float(hi));
}
__device__ __forceinline__ void mma_tf32(float* d, const uint32_t* a,
                                         uint32_t b0, uint32_t b1) {
    asm volatile("mma.sync.aligned.m16n8k8.row.col.f32.tf32.tf32.f32 "
                 "{%0,%1,%2,%3}, {%4,%5,%6,%7}, {%8,%9}, {%0,%1,%2,%3};"
                 : "+f"(d[0]), "+f"(d[1]), "+f"(d[2]), "+f"(d[3])
                 : "r"(a[0]), "r"(a[1]), "r"(a[2]), "r"(a[3]), "r"(b0), "r"(b1));
}
// ---- TMA + mbarrier ----
__device__ __forceinline__ void tma2d(uint32_t dst, const void* map,
                                      int c0, int c1, uint32_t mbar) {
    asm volatile("cp.async.bulk.tensor.2d.shared::cta.global.tile.mbarrier::complete_tx::bytes "
                 "[%0], [%1, {%2, %3}], [%4];"
                 :: "r"(dst), "l"(map), "r"(c0), "r"(c1), "r"(mbar) : "memory");
}
__device__ __forceinline__ void tma3d(uint32_t dst, const void* map,
                                      int c0, int c1, int c2, uint32_t mbar) {
    asm volatile("cp.async.bulk.tensor.3d.shared::cta.global.tile.mbarrier::complete_tx::bytes "
                 "[%0], [%1, {%2, %3, %4}], [%5];"
                 :: "r"(dst), "l"(map), "r"(c0), "r"(c1), "r"(c2), "r"(mbar) : "memory");
}
__device__ __forceinline__ void mbar_init(uint32_t mbar, uint32_t cnt) {
    asm volatile("mbarrier.init.shared.b64 [%0], %1;" :: "r"(mbar), "r"(cnt) : "memory");
}
__device__ __forceinline__ void mbar_expect(uint32_t mbar, uint32_t bytes) {
    asm volatile("mbarrier.arrive.expect_tx.shared.b64 _, [%0], %1;"
                 :: "r"(mbar), "r"(bytes) : "memory");
}
__device__ __forceinline__ void mbar_wait(uint32_t mbar, uint32_t parity) {
    uint32_t done;
    asm volatile("{\n\t.reg .pred p;\n\t"
                 "mbarrier.try_wait.parity.acquire.cta.shared::cta.b64 p, [%1], %2;\n\t"
                 "selp.b32 %0, 1, 0, p;\n\t}"
                 : "=r"(done) : "r"(mbar), "r"(parity) : "memory");
    while (!done) {
        asm volatile("{\n\t.reg .pred p;\n\t"
                     "mbarrier.try_wait.parity.acquire.cta.shared::cta.b64 p, [%1], %2;\n\t"
                     "selp.b32 %0, 1, 0, p;\n\t}"
                     : "=r"(done) : "r"(mbar), "r"(parity) : "memory");
    }
}

// ===========================================================================
// Kernel 1: encode / spmm (UNCHANGED — proven 259.9us spmm from r9/r10)
// ===========================================================================
#define NSTAGE     3
#define STAGE_B    32768u
#define DATA_OFF   1024u
#define SMEM_BYTES (DATA_OFF + NSTAGE * STAGE_B)

template<int MODE, bool SPMM, int K>
__global__ void __launch_bounds__(256, 2)
gemm_tma(const __grid_constant__ CUtensorMap mA1,
         const __grid_constant__ CUtensorMap mB1,
         const float* __restrict__ bias1,
         const float* __restrict__ ffd, float* __restrict__ Cout)
{
    extern __shared__ __align__(1024) char smem[];
    const uint32_t sb = smem_u32(smem);

    const int tid = threadIdx.x, lane = tid & 31, warp = tid >> 5;
    const int wm = warp & 3, wn = warp >> 2;
    const int mbase = wm * 32, nbase = wn * 64;
    const int lq = lane >> 2, lt = lane & 3;

    const size_t rowTile = SPMM ? ((size_t)blockIdx.y * SEQ + (size_t)blockIdx.x * 128)
                                : ((size_t)blockIdx.x * 128);
    constexpr int NC = K / 32;

    if (tid == 0) {
#pragma unroll
        for (int s = 0; s < NSTAGE; s++) mbar_init(sb + s * 8, 1);
    }
    __syncthreads();

    auto issue = [&](int c) {
        const int s = c % NSTAGE;
        const uint32_t bar  = sb + s * 8;
        const uint32_t dstA = sb + DATA_OFF + s * STAGE_B;
        const uint32_t dstB = dstA + 16384u;
        const int k0 = c * 32;
        mbar_expect(bar, STAGE_B);
        if (SPMM) tma3d(dstA, &mA1, k0, (int)(blockIdx.x * 128), (int)blockIdx.y, bar);
        else      tma2d(dstA, &mA1, k0, (int)(blockIdx.x * 128), bar);
        const int brow = SPMM ? (int)(blockIdx.y * SEQ + k0) : k0;
#pragma unroll
        for (int i = 0; i < 4; i++)
            tma2d(dstB + i * 4096u, &mB1, i * 32, brow, bar);
    };

    float acc[2][8][4];
#pragma unroll
    for (int mi = 0; mi < 2; mi++)
#pragma unroll
        for (int j = 0; j < 8; j++)
#pragma unroll
            for (int q = 0; q < 4; q++) acc[mi][j][q] = 0.0f;

    const uint32_t aswz = (uint32_t)lq << 4;
    uint32_t bcol0[8], bcol1[8];
#pragma unroll
    for (int j = 0; j < 8; j++) {
        const int n  = nbase + j * 8 + lq;
        const uint32_t nb = (uint32_t)((n & 31) * 4);
        bcol0[j] = ((uint32_t)(n >> 5)) * 4096u + (nb ^ ((uint32_t)lt << 4));
        bcol1[j] = ((uint32_t)(n >> 5)) * 4096u + (nb ^ (((uint32_t)(lt + 4)) << 4));
    }

    if (tid == 0) {
        issue(0);
        if (NC > 1) issue(1);
        if (NC > 2) issue(2);
    }

#pragma unroll 1
    for (int c = 0; c < NC; ++c) {
        const int s = c % NSTAGE;
        mbar_wait(sb + s * 8, (uint32_t)((c / NSTAGE) & 1));
        const char* As = smem + DATA_OFF + s * STAGE_B;
        const char* Bs = As + 16384;

#pragma unroll
        for (int kk = 0; kk < 32; kk += 8) {
            const int kt0 = kk + lt, kt1 = kt0 + 4;
            uint32_t ah[2][4], al[2][4];
#pragma unroll
            for (int mi = 0; mi < 2; mi++) {
                const int r0 = mbase + mi * 16 + lq, r1 = r0 + 8;
                const uint32_t c0 = ((uint32_t)(kt0 * 4)) ^ aswz;
                const uint32_t c1 = ((uint32_t)(kt1 * 4)) ^ aswz;
                tsplit(*(const float*)(As + r0 * 128 + c0), ah[mi][0], al[mi][0]);
                tsplit(*(const float*)(As + r1 * 128 + c0), ah[mi][1], al[mi][1]);
                tsplit(*(const float*)(As + r0 * 128 + c1), ah[mi][2], al[mi][2]);
                tsplit(*(const float*)(As + r1 * 128 + c1), ah[mi][3], al[mi][3]);
            }
#pragma unroll
            for (int j = 0; j < 8; j++) {
                uint32_t bh0, bl0, bh1, bl1;
                tsplit(*(const float*)(Bs + kt0 * 128 + bcol0[j]), bh0, bl0);
                tsplit(*(const float*)(Bs + kt1 * 128 + bcol1[j]), bh1, bl1);
#pragma unroll
                for (int mi = 0; mi < 2; mi++) {
                    mma_tf32(acc[mi][j], ah[mi], bh0, bh1);
                    mma_tf32(acc[mi][j], ah[mi], bl0, bl1);
                    mma_tf32(acc[mi][j], al[mi], bh0, bh1);
                }
            }
        }
        __syncthreads();
        if (c + NSTAGE < NC && tid == 0) issue(c + NSTAGE);
    }

#pragma unroll
    for (int mi = 0; mi < 2; mi++) {
        const int rA = mbase + mi * 16 + lq;
        const size_t gr0 = rowTile + rA, gr1 = gr0 + 8;
        float s0 = 1.0f, s1 = 1.0f;
        if (MODE == 4) { s0 += ffd[gr0]; s1 += ffd[gr1]; }
#pragma unroll
        for (int j = 0; j < 8; j++) {
            const int col = nbase + j * 8 + lt * 2;
            float o[4];
#pragma unroll
            for (int q = 0; q < 4; q++) {
                const int cc = col + (q & 1);
                float v = acc[mi][j][q];
                if (MODE == 0) v = fmaxf(v + bias1[cc], 0.0f);
                else           v = v * ((q < 2) ? s0 : s1);
                o[q] = v;
            }
            *(float2*)&Cout[gr0 * 128 + col] = make_float2(o[0], o[1]);
            *(float2*)&Cout[gr1 * 128 + col] = make_float2(o[2], o[3]);
        }
    }
}

// ===========================================================================
// Kernel 2: fused GRU gates v5 — weights via DIRECT LDG (L2-hot), no weight
// smem/mbarriers/per-chunk syncs. 64-row tile, 256 threads (2Mx4N), 2 CTA/SM.
// Pass order (identical numerics to r9 v2.1):
//   p0 Wz0(a), p1 Wz1(h) -> z(regs); p2 Wr0(a), p3 Wr1(h) -> ro=r*h -> H
//   (double-barriered); p4 Wh0(a), p5 Wh1(ro) -> h'=relu(.+bh)*z + h*(1-z)
// ===========================================================================
#define G_A    1024u
#define G_H    (G_A + 32768u)
#define G_SMEM (G_H + 32768u)    // 66560

__global__ void __launch_bounds__(256, 2)
fused_gate(const __grid_constant__ CUtensorMap mA,
           const __grid_constant__ CUtensorMap mH,
           const float* __restrict__ Wz0, const float* __restrict__ Wz1,
           const float* __restrict__ Wr0, const float* __restrict__ Wr1,
           const float* __restrict__ Wh0, const float* __restrict__ Wh1,
           const float* __restrict__ bz0, const float* __restrict__ bz1,
           const float* __restrict__ br0, const float* __restrict__ br1,
           const float* __restrict__ bh0, const float* __restrict__ bh1,
           const float* Hg, float* OutH)
{
    extern __shared__ __align__(1024) char smem[];
    const uint32_t sb = smem_u32(smem);

    const int tid = threadIdx.x, lane = tid & 31, warp = tid >> 5;
    const int wm = warp & 1, wn = warp >> 1;
    const int mbase = wm * 32, nbase = wn * 32;
    const int lq = lane >> 2, lt = lane & 3;
    const int row0 = (int)(blockIdx.x * 64);

    if (tid == 0) {
        mbar_init(sb + 0, 1);
        mbar_expect(sb + 0, 65536u);
#pragma unroll
        for (int i = 0; i < 4; i++) {
            tma2d(sb + G_A + i * 8192u, &mA, i * 32, row0, sb + 0);
            tma2d(sb + G_H + i * 8192u, &mH, i * 32, row0, sb + 0);
        }
    }
    __syncthreads();

    float acc[2][4][4], zreg[2][4][4];
#pragma unroll
    for (int mi = 0; mi < 2; mi++)
#pragma unroll
        for (int j = 0; j < 4; j++)
#pragma unroll
            for (int q = 0; q < 4; q++) acc[mi][j][q] = 0.0f;

    // per-thread weight column indices (j -> n)
    int ncol[4];
#pragma unroll
    for (int j = 0; j < 4; j++) ncol[j] = nbase + j * 8 + lq;

    // byte offset of element (row r, col c) in a 64-row tile region
    auto toff = [&](uint32_t region, int r, int c) -> uint32_t {
        return region + (uint32_t)(c >> 5) * 8192u + (uint32_t)r * 128u
               + (((uint32_t)((c & 31) * 4)) ^ ((uint32_t)(r & 7) << 4));
    };

    const float* wptr[6] = {Wz0, Wz1, Wr0, Wr1, Wh0, Wh1};

    mbar_wait(sb + 0, 0);   // a & h tiles resident

#pragma unroll 1
    for (int q = 0; q < 24; ++q) {
        const int p = q >> 2, c = q & 3;
        const uint32_t Areg = (p == 1 || p == 3 || p == 5) ? G_H : G_A;
        const float* __restrict__ W = wptr[p];

#pragma unroll
        for (int kk = 0; kk < 32; kk += 8) {
            const int kt0 = c * 32 + kk + lt, kt1 = kt0 + 4;
            uint32_t ah[2][4], al[2][4];
#pragma unroll
            for (int mi = 0; mi < 2; mi++) {
                const int r0 = mbase + mi * 16 + lq, r1 = r0 + 8;
                tsplit(*(const float*)(smem + toff(Areg, r0, kt0)), ah[mi][0], al[mi][0]);
                tsplit(*(const float*)(smem + toff(Areg, r1, kt0)), ah[mi][1], al[mi][1]);
                tsplit(*(const float*)(smem + toff(Areg, r0, kt1)), ah[mi][2], al[mi][2]);
                tsplit(*(const float*)(smem + toff(Areg, r1, kt1)), ah[mi][3], al[mi][3]);
            }
#pragma unroll
            for (int j = 0; j < 4; j++) {
                uint32_t bh0, bl0, bh1, bl1;
                tsplit(__ldg(W + kt0 * 128 + ncol[j]), bh0, bl0);
                tsplit(__ldg(W + kt1 * 128 + ncol[j]), bh1, bl1);
#pragma unroll
                for (int mi = 0; mi < 2; mi++) {
                    mma_tf32(acc[mi][j], ah[mi], bh0, bh1);
                    mma_tf32(acc[mi][j], ah[mi], bl0, bl1);
                    mma_tf32(acc[mi][j], al[mi], bh0, bh1);
                }
            }
        }

        if (q == 7) {       // z = sigmoid(acc + bz); keep in regs; reset acc
#pragma unroll
            for (int mi = 0; mi < 2; mi++)
#pragma unroll
                for (int j = 0; j < 4; j++)
#pragma unroll
                    for (int qq = 0; qq < 4; qq++) {
                        const int cc = nbase + j * 8 + lt * 2 + (qq & 1);
                        zreg[mi][j][qq] = sigmoidf_(acc[mi][j][qq] + bz0[cc] + bz1[cc]);
                        acc[mi][j][qq] = 0.0f;
                    }
        }
        if (q == 15) {
            // compute ro into regs (H reads), barrier so ALL warps (which have
            // each reached q==15) have finished every H read of passes 2-3,
            // then overwrite H; second barrier orders writes before pass-5 reads.
#pragma unroll
            for (int mi = 0; mi < 2; mi++) {
                const int r0 = mbase + mi * 16 + lq;
#pragma unroll
                for (int j = 0; j < 4; j++)
#pragma unroll
                    for (int qq = 0; qq < 4; qq++) {
                        const int cc = nbase + j * 8 + lt * 2 + (qq & 1);
                        const int rr = (qq < 2) ? r0 : r0 + 8;
                        const float rv = sigmoidf_(acc[mi][j][qq] + br0[cc] + br1[cc]);
                        const float hv = *(const float*)(smem + toff(G_H, rr, cc));
                        acc[mi][j][qq] = rv * hv;
                    }
            }
            __syncthreads();     // all warps done READING H
#pragma unroll
            for (int mi = 0; mi < 2; mi++) {
                const int r0 = mbase + mi * 16 + lq;
#pragma unroll
                for (int j = 0; j < 4; j++)
#pragma unroll
                    for (int qq = 0; qq < 4; qq++) {
                        const int cc = nbase + j * 8 + lt * 2 + (qq & 1);
                        const int rr = (qq < 2) ? r0 : r0 + 8;
                        *(float*)(smem + toff(G_H, rr, cc)) = acc[mi][j][qq];
                        acc[mi][j][qq] = 0.0f;
                    }
            }
            __syncthreads();     // H writes visible before pass-5 reads
        }
    }

    // epilogue: h' = relu(acc + bh)*z + h_gmem*(1-z)
#pragma unroll
    for (int mi = 0; mi < 2; mi++) {
        const int r0 = mbase + mi * 16 + lq;
        const size_t gr0 = (size_t)row0 + r0, gr1 = gr0 + 8;
#pragma unroll
        for (int j = 0; j < 4; j++) {
            const int col = nbase + j * 8 + lt * 2;
            const float2 h0 = *(const float2*)&Hg[gr0 * 128 + col];
            const float2 h1 = *(const float2*)&Hg[gr1 * 128 + col];
            float o[4];
            const float hv[4] = {h0.x, h0.y, h1.x, h1.y};
#pragma unroll
            for (int qq = 0; qq < 4; qq++) {
                const int cc = col + (qq & 1);
                const float zv = zreg[mi][j][qq];
                o[qq] = fmaxf(acc[mi][j][qq] + bh0[cc] + bh1[cc], 0.0f) * zv
                        + hv[qq] * (1.0f - zv);
            }
            *(float2*)&OutH[gr0 * 128 + col] = make_float2(o[0], o[1]);
            *(float2*)&OutH[gr1 * 128 + col] = make_float2(o[2], o[3]);
        }
    }
}

// ---------------------------------------------------------------------------
// host side
// ---------------------------------------------------------------------------
typedef CUresult (*pfn_encode_t)(CUtensorMap*, CUtensorMapDataType, cuuint32_t,
                                 void*, const cuuint64_t*, const cuuint64_t*,
                                 const cuuint32_t*, const cuuint32_t*,
                                 CUtensorMapInterleave, CUtensorMapSwizzle,
                                 CUtensorMapL2promotion, CUtensorMapFloatOOBfill);
static pfn_encode_t enc_fn = nullptr;

static void map2d(CUtensorMap* m, const void* ptr, uint64_t d0, uint64_t d1,
                  uint32_t b0, uint32_t b1) {
    cuuint64_t dims[2]    = {d0, d1};
    cuuint64_t strides[1] = {d0 * 4};
    cuuint32_t box[2]     = {b0, b1};
    cuuint32_t es[2]      = {1, 1};
    enc_fn(m, CU_TENSOR_MAP_DATA_TYPE_FLOAT32, 2, (void*)ptr, dims, strides, box, es,
           CU_TENSOR_MAP_INTERLEAVE_NONE, CU_TENSOR_MAP_SWIZZLE_128B,
           CU_TENSOR_MAP_L2_PROMOTION_L2_128B, CU_TENSOR_MAP_FLOAT_OOB_FILL_NONE);
}
static void map3d_sup(CUtensorMap* m, const void* ptr) {
    cuuint64_t dims[3]    = {SEQ, SEQ, BATCH};
    cuuint64_t strides[2] = {(uint64_t)SEQ * 4, (uint64_t)SEQ * SEQ * 4};
    cuuint32_t box[3]     = {32, 128, 1};
    cuuint32_t es[3]      = {1, 1, 1};
    enc_fn(m, CU_TENSOR_MAP_DATA_TYPE_FLOAT32, 3, (void*)ptr, dims, strides, box, es,
           CU_TENSOR_MAP_INTERLEAVE_NONE, CU_TENSOR_MAP_SWIZZLE_128B,
           CU_TENSOR_MAP_L2_PROMOTION_L2_128B, CU_TENSOR_MAP_FLOAT_OOB_FILL_NONE);
}

extern "C" void kernel_launch(void* const* d_in, const int* in_sizes, int n_in,
                              void* d_out, int out_size)
{
    const float* x       = (const float*)d_in[0];
    const float* support = (const float*)d_in[1];
    const float* ffd     = (const float*)d_in[2];
    // d_in[3] = mask (unused by reference)
    const float* We  = (const float*)d_in[4];
    const float* be  = (const float*)d_in[5];
    const float* Wz0 = (const float*)d_in[6];
    const float* bz0 = (const float*)d_in[7];
    const float* Wz1 = (const float*)d_in[8];
    const float* bz1 = (const float*)d_in[9];
    const float* Wr0 = (const float*)d_in[10];
    const float* br0 = (const float*)d_in[11];
    const float* Wr1 = (const float*)d_in[12];
    const float* br1 = (const float*)d_in[13];
    const float* Wh0 = (const float*)d_in[14];
    const float* bh0 = (const float*)d_in[15];
    const float* Wh1 = (const float*)d_in[16];
    const float* bh1 = (const float*)d_in[17];

    float *h, *a;
    cudaGetSymbolAddress((void**)&h, g_h);
    cudaGetSymbolAddress((void**)&a, g_a);

    if (!enc_fn) {
        cudaDriverEntryPointQueryResult qr;
        cudaGetDriverEntryPoint("cuTensorMapEncodeTiled", (void**)&enc_fn,
                                cudaEnableDefault, &qr);
    }

    CUtensorMap m_sup, m_x, m_hB, m_a64, m_h64, m_We;
    map3d_sup(&m_sup, support);
    map2d(&m_x,   x, DIM, MTOT, 32, 128);
    map2d(&m_hB,  h, DIM, MTOT, 32, 32);
    map2d(&m_a64, a, DIM, MTOT, 32, 64);
    map2d(&m_h64, h, DIM, MTOT, 32, 64);
    map2d(&m_We,  We, DIM, DIM, 32, 32);

    cudaFuncSetAttribute(gemm_tma<0, false, 128>, cudaFuncAttributeMaxDynamicSharedMemorySize, SMEM_BYTES);
    cudaFuncSetAttribute(gemm_tma<4, true, 2048>, cudaFuncAttributeMaxDynamicSharedMemorySize, SMEM_BYTES);
    cudaFuncSetAttribute(fused_gate, cudaFuncAttributeMaxDynamicSharedMemorySize, G_SMEM);

    const dim3 grd_enc(MTOT / 128);            // 256
    const dim3 grd_spmm(SEQ / 128, BATCH);     // (16,16)
    const dim3 grd_fused(MTOT / 64);           // 512

    // h = relu(x @ We + be)
    gemm_tma<0, false, 128><<<grd_enc, 256, SMEM_BYTES>>>(m_x, m_We, be, nullptr, h);

    for (int t = 0; t < 2; ++t) {
        // a = (support @ h) * (1 + FFD)
        gemm_tma<4, true, 2048><<<grd_spmm, 256, SMEM_BYTES>>>(m_sup, m_hB, nullptr, ffd, a);
        // fused gates + GRU combine (weights via direct LDG)
        float* dst = (t == 1) ? (float*)d_out : h;
        fused_gate<<<grd_fused, 256, G_SMEM>>>(m_a64, m_h64,
                                               Wz0, Wz1, Wr0, Wr1, Wh0, Wh1,
                                               bz0, bz1, br0, br1, bh0, bh1, h, dst);
    }
}